// round 15
// baseline (speedup 1.0000x reference)
#include <cuda_runtime.h>
#include <cuda_bf16.h>
#include <math.h>
#include <stdint.h>

// ---------------- problem constants ----------------
#define DIMM   1024
#define NHEADS 8
#define DHEAD  128
#define NTOK   2049
#define BATCH  2
#define MROWS  (BATCH*NTOK)  // 4098
#define HID    4096
#define L_HEAD 4
#define L_TAIL 4

// ---------------- scratch (device globals) ----------------
__device__ __align__(16) float g_x  [(size_t)MROWS*DIMM];
__device__ __align__(16) float g_cls[(size_t)BATCH*DIMM];

__device__ __align__(16) unsigned g_xs_h[(size_t)MROWS*DIMM/2];
__device__ __align__(16) unsigned g_xs_l[(size_t)MROWS*DIMM/2];
__device__ __align__(16) unsigned g_as_h[(size_t)MROWS*DIMM/2];
__device__ __align__(16) unsigned g_as_l[(size_t)MROWS*DIMM/2];
__device__ __align__(16) unsigned g_hs_h[(size_t)MROWS*HID/2];
__device__ __align__(16) unsigned g_hs_l[(size_t)MROWS*HID/2];
__device__ __align__(16) unsigned g_qs_h[(size_t)MROWS*3*DIMM/2];
__device__ __align__(16) unsigned g_qs_l[(size_t)MROWS*3*DIMM/2];

// weight splits, frag-pair layout:
//   word offset (per layer) = (g8*N + n)*8 + q*2 + h,  k2 = 8*g8 + q + 4*h
#define WQKV_L (512*3072)
#define WO_L   (512*1024)
#define W1_L   (512*4096)
#define W2_L   (2048*1024)
__device__ __align__(16) unsigned g_wqkv_h[8*(size_t)WQKV_L];
__device__ __align__(16) unsigned g_wqkv_l[8*(size_t)WQKV_L];
__device__ __align__(16) unsigned g_wo_h[8*(size_t)WO_L];
__device__ __align__(16) unsigned g_wo_l[8*(size_t)WO_L];
__device__ __align__(16) unsigned g_w1_h[8*(size_t)W1_L];
__device__ __align__(16) unsigned g_w1_l[8*(size_t)W1_L];
__device__ __align__(16) unsigned g_w2_h[8*(size_t)W2_L];
__device__ __align__(16) unsigned g_w2_l[8*(size_t)W2_L];

// ---------------- bf16 helpers ----------------
__device__ __forceinline__ unsigned short f2bf(float x) {
    __nv_bfloat16 h = __float2bfloat16(x);
    return *reinterpret_cast<unsigned short*>(&h);
}
__device__ __forceinline__ float bf2f(unsigned short s) {
    __nv_bfloat16 h = *reinterpret_cast<__nv_bfloat16*>(&s);
    return __bfloat162float(h);
}
__device__ __forceinline__ void split_bf16(float x, unsigned short& hi, unsigned short& lo) {
    hi = f2bf(x);
    lo = f2bf(x - bf2f(hi));
}
__device__ __forceinline__ void split_pair(float a, float b, unsigned& hw, unsigned& lw) {
    unsigned short ah, al, bh, bl;
    split_bf16(a, ah, al);
    split_bf16(b, bh, bl);
    hw = (unsigned)ah | ((unsigned)bh << 16);
    lw = (unsigned)al | ((unsigned)bl << 16);
}

__device__ __forceinline__ void mma_bf16(float* c, const unsigned* a, const unsigned* b) {
    asm("mma.sync.aligned.m16n8k16.row.col.f32.bf16.bf16.f32 "
        "{%0,%1,%2,%3}, {%4,%5,%6,%7}, {%8,%9}, {%0,%1,%2,%3};"
        : "+f"(c[0]), "+f"(c[1]), "+f"(c[2]), "+f"(c[3])
        : "r"(a[0]), "r"(a[1]), "r"(a[2]), "r"(a[3]),
          "r"(b[0]), "r"(b[1]));
}

__device__ __forceinline__ void ldsm4(unsigned* r, const void* p) {
    unsigned a = (unsigned)__cvta_generic_to_shared(p);
    asm volatile("ldmatrix.sync.aligned.m8n8.x4.shared.b16 {%0,%1,%2,%3}, [%4];"
        : "=r"(r[0]), "=r"(r[1]), "=r"(r[2]), "=r"(r[3]) : "r"(a));
}

__device__ __forceinline__ void cpa16(void* dst, const void* src, int sz) {
    unsigned d = (unsigned)__cvta_generic_to_shared(dst);
    asm volatile("cp.async.cg.shared.global [%0], [%1], 16, %2;" :: "r"(d), "l"(src), "r"(sz));
}
__device__ __forceinline__ void cp_commit() { asm volatile("cp.async.commit_group;"); }
template<int N> __device__ __forceinline__ void cp_wait() {
    asm volatile("cp.async.wait_group %0;" :: "n"(N));
}

// ---------------- weight pre-split kernel (frag-pair layout, tiled/coalesced) ----------
__global__ void split_w2_kernel(const float* __restrict__ Wh, const float* __restrict__ Wt,
                                unsigned* __restrict__ oH, unsigned* __restrict__ oL,
                                int K, int N)
{
    __shared__ unsigned smh[8][257], sml[8][257];
    int l = blockIdx.z;
    const float* W = (l < 4) ? (Wh + (size_t)l * K * N) : (Wt + (size_t)(l - 4) * K * N);
    int g8 = blockIdx.y;
    int n0 = blockIdx.x * 256;
    int tx = threadIdx.x;
#pragma unroll
    for (int r = 0; r < 8; r++) {
        int k2 = g8 * 8 + r;
        float a = W[(size_t)(2 * k2) * N + n0 + tx];
        float b = W[(size_t)(2 * k2 + 1) * N + n0 + tx];
        unsigned hw, lw;
        split_pair(a, b, hw, lw);
        smh[r][tx] = hw;
        sml[r][tx] = lw;
    }
    __syncthreads();
    size_t base = (size_t)l * ((size_t)K * N / 2) + ((size_t)g8 * N + n0 + tx) * 8;
    unsigned vh[8], vl[8];
#pragma unroll
    for (int j = 0; j < 8; j++) {
        int r = (j >> 1) + 4 * (j & 1);
        vh[j] = smh[r][tx];
        vl[j] = sml[r][tx];
    }
    *(uint4*)(oH + base)     = make_uint4(vh[0], vh[1], vh[2], vh[3]);
    *(uint4*)(oH + base + 4) = make_uint4(vh[4], vh[5], vh[6], vh[7]);
    *(uint4*)(oL + base)     = make_uint4(vl[0], vl[1], vl[2], vl[3]);
    *(uint4*)(oL + base + 4) = make_uint4(vl[4], vl[5], vl[6], vl[7]);
}

// ---------------- concat cls + x ----------------
__global__ void concat_kernel(const float* __restrict__ x, const float* __restrict__ cls,
                              float* __restrict__ gx,
                              unsigned* __restrict__ xh, unsigned* __restrict__ xl)
{
    int idx = blockIdx.x * blockDim.x + threadIdx.x;
    int total = MROWS * DIMM / 2;
    if (idx >= total) return;
    int c2  = idx % (DIMM / 2);
    int row = idx / (DIMM / 2);
    int n = row % NTOK, b = row / NTOK;
    float v0, v1;
    if (n == 0) { v0 = cls[c2 * 2]; v1 = cls[c2 * 2 + 1]; }
    else {
        const float* p = x + ((size_t)b * (NTOK - 1) + (n - 1)) * DIMM + c2 * 2;
        v0 = p[0]; v1 = p[1];
    }
    gx[idx * 2] = v0; gx[idx * 2 + 1] = v1;
    unsigned hw, lw;
    split_pair(v0, v1, hw, lw);
    xh[idx] = hw; xl[idx] = lw;
}

// ---------------- tensor-core GEMM: 4 warps, warp tile 64x64, 3-stage, 2 CTAs/SM --------
#define AST_B 80
#define STG_A (128*AST_B)               // 10240 per A plane
#define BGRP  1032                      // words per k-group (1024 data + 8 pad)
#define STG_B4 (2*BGRP*4)               // 8256 bytes per B plane
#define STG_BYTES (2*STG_A + 2*STG_B4)  // 36992
#define NSTAGE 3
#define SM_TOTAL (NSTAGE*STG_BYTES)     // 110976

template<bool BIAS, bool RESID, bool DOGELU, bool W32, bool WS>
__global__ __launch_bounds__(128, 2)
void tgemm_kernel(const unsigned* __restrict__ AH, const unsigned* __restrict__ AL,
                  const unsigned* __restrict__ BH, const unsigned* __restrict__ BL,
                  const float* __restrict__ bias, const float* __restrict__ R,
                  float* __restrict__ C,
                  unsigned* __restrict__ OH, unsigned* __restrict__ OL,
                  int M, int K, int N)
{
    extern __shared__ char smem[];

    const int t    = threadIdx.x;
    const int warp = t >> 5;
    const int lane = t & 31;
    const int g    = lane >> 2;
    const int q    = lane & 3;
    const int wm   = warp & 1;    // 64-row slab
    const int wn   = warp >> 1;   // 64-col slab
    const int bm   = blockIdx.y * 128;
    const int bn   = blockIdx.x * 128;
    const int steps = K >> 5;

    float acc[4][8][4];
#pragma unroll
    for (int i = 0; i < 4; i++)
#pragma unroll
        for (int j = 0; j < 8; j++)
#pragma unroll
            for (int e = 0; e < 4; e++) acc[i][j][e] = 0.f;

    const unsigned short* AHg = (const unsigned short*)AH;
    const unsigned short* ALg = (const unsigned short*)AL;

    auto issue = [&](int s) {
        char* buf = smem + (s % NSTAGE) * STG_BYTES;
        char* AHs = buf;
        char* ALs = buf + STG_A;
        char* BHs = buf + 2 * STG_A;
        char* BLs = buf + 2 * STG_A + STG_B4;
        int k0 = s * 32;
        // A: 512 chunks per plane, 4 per thread per plane
#pragma unroll
        for (int i = 0; i < 4; i++) {
            int idx = i * 128 + t;
            int row = idx >> 2, sub = idx & 3;
            int gr = bm + row;
            int sz = (gr < M) ? 16 : 0;
            size_t so = (size_t)(gr < M ? gr : 0) * K + k0 + sub * 8;
            cpa16(AHs + row * AST_B + sub * 16, AHg + so, sz);
            cpa16(ALs + row * AST_B + sub * 16, ALg + so, sz);
        }
        // B: 2 contiguous 1024-word groups per plane, 4 chunks per thread per plane
        int sgrp = s * 2;
#pragma unroll
        for (int i = 0; i < 4; i++) {
            int idx = i * 128 + t;
            int grp = idx >> 8, j = idx & 255;
            size_t src = ((size_t)(sgrp + grp) * N + bn) * 8 + j * 4;
            int db = grp * (BGRP * 4) + j * 16;
            cpa16(BHs + db, BH + src, 16);
            cpa16(BLs + db, BL + src, 16);
        }
        cp_commit();
    };

    issue(0);
    if (steps > 1) issue(1);

    const int lanebase = (wm * 64 + (lane & 7) + ((lane >> 3) & 1) * 8) * AST_B + (lane >> 4) * 16;

    for (int s = 0; s < steps; s++) {
        if (s + 1 < steps) cp_wait<1>();
        else               cp_wait<0>();
        __syncthreads();

        if (s + 2 < steps) issue(s + 2);

        const char* buf = smem + (s % NSTAGE) * STG_BYTES;
        const char* AHs = buf;
        const char* ALs = buf + STG_A;
        const unsigned* BHw = (const unsigned*)(buf + 2 * STG_A);
        const unsigned* BLw = (const unsigned*)(buf + 2 * STG_A + STG_B4);

#pragma unroll
        for (int ko = 0; ko < 2; ko++) {
            unsigned bh[8][2], bl[8][2];
#pragma unroll
            for (int ni = 0; ni < 8; ni++) {
                int ad = ko * BGRP + (wn * 64 + g + ni * 8) * 8 + q * 2;
                uint2 vh2 = *(const uint2*)(BHw + ad);
                uint2 vl2 = *(const uint2*)(BLw + ad);
                bh[ni][0] = vh2.x; bh[ni][1] = vh2.y;
                bl[ni][0] = vl2.x; bl[ni][1] = vl2.y;
            }
#pragma unroll
            for (int mi = 0; mi < 4; mi++) {
                unsigned ah[4], al[4];
                ldsm4(ah, AHs + lanebase + mi * (16 * AST_B) + ko * 32);
                ldsm4(al, ALs + lanebase + mi * (16 * AST_B) + ko * 32);
#pragma unroll
                for (int ni = 0; ni < 8; ni++) {
                    mma_bf16(acc[mi][ni], ah, bh[ni]);
                    mma_bf16(acc[mi][ni], ah, bl[ni]);
                    mma_bf16(acc[mi][ni], al, bh[ni]);
                }
            }
        }
    }

    // ---- epilogue ----
    const int Nw = N >> 1;
#pragma unroll
    for (int mi = 0; mi < 4; mi++) {
        int r0 = bm + wm * 64 + mi * 16 + g;
#pragma unroll
        for (int ni = 0; ni < 8; ni++) {
            int cb = bn + wn * 64 + ni * 8 + 2 * q;
            float v[4];
#pragma unroll
            for (int e = 0; e < 4; e++) {
                v[e] = acc[mi][ni][e];
                if (BIAS) v[e] += bias[cb + (e & 1)];
                if (DOGELU) v[e] = 0.5f * v[e] * (1.f + erff(v[e] * 0.70710678118f));
            }
#pragma unroll
            for (int half = 0; half < 2; half++) {
                int gr = r0 + half * 8;
                if (gr >= M) continue;
                float a = v[half * 2], b = v[half * 2 + 1];
                if (RESID) {
                    a += R[(size_t)gr * N + cb];
                    b += R[(size_t)gr * N + cb + 1];
                }
                if (W32) {
                    C[(size_t)gr * N + cb]     = a;
                    C[(size_t)gr * N + cb + 1] = b;
                }
                if (WS) {
                    unsigned hw, lw;
                    split_pair(a, b, hw, lw);
                    size_t wi = (size_t)gr * Nw + (cb >> 1);
                    OH[wi] = hw;
                    OL[wi] = lw;
                }
            }
        }
    }
}

// ---------------- flash attention: double-buffered K (cp.async) + V (reg prefetch) -------
#define ATT_PW 4352
#define ATT_SMEM (10*ATT_PW*4)   // 174080 bytes

__global__ __launch_bounds__(128, 1)
void fattn_kernel(const unsigned* __restrict__ QVH, const unsigned* __restrict__ QVL,
                  unsigned* __restrict__ OH, unsigned* __restrict__ OL)
{
    extern __shared__ unsigned smw[];
    unsigned* QH = smw;
    unsigned* QL = QH + ATT_PW;
    unsigned* KH = QL + ATT_PW;
    unsigned* KL = KH + 2*ATT_PW;
    unsigned* VH = KL + 2*ATT_PW;
    unsigned* VL = VH + 2*ATT_PW;

    const int t    = threadIdx.x;
    const int lane = t & 31;
    const int w    = t >> 5;
    const int g    = lane >> 2;
    const int q    = lane & 3;
    const int qt   = 32 - blockIdx.x;
    const int bh   = blockIdx.y;
    const int h    = bh & 7;
    const int b    = bh >> 3;
    const float scale = 0.03125f;

    const unsigned* bHp = QVH + (size_t)b * NTOK * 1536;
    const unsigned* bLp = QVL + (size_t)b * NTOK * 1536;

    unsigned vpre[8][8];

    auto stageK = [&](int jt, int p) {
        unsigned* KHp = KH + p * ATT_PW;
        unsigned* KLp = KL + p * ATT_PW;
#pragma unroll
        for (int i = 0; i < 8; i++) {
            int idx = i * 128 + t;
            int key = idx >> 4;
            int c4w = (idx & 15) * 4;
            int gkey = jt * 64 + key;
            int sz = (gkey < NTOK) ? 16 : 0;
            size_t gw = (size_t)(gkey < NTOK ? gkey : 0) * 1536 + 512 + h * 64 + c4w;
            cpa16(KHp + key * 68 + c4w, bHp + gw, sz);
            cpa16(KLp + key * 68 + c4w, bLp + gw, sz);
        }
        cp_commit();
    };

    auto loadV = [&](int jt) {
#pragma unroll
        for (int i = 0; i < 8; i++) {
            int idx = i * 128 + t;
            int kp = idx >> 5;
            int cg = idx & 31;
            int k0g = jt * 64 + 2 * kp;
            uint2 wh = make_uint2(0,0), uh = make_uint2(0,0);
            uint2 wl = make_uint2(0,0), ul = make_uint2(0,0);
            if (k0g < NTOK) {
                size_t gw = (size_t)k0g * 1536 + 1024 + h * 64 + 2 * cg;
                wh = *(const uint2*)(bHp + gw);
                wl = *(const uint2*)(bLp + gw);
            }
            if (k0g + 1 < NTOK) {
                size_t gw = (size_t)(k0g + 1) * 1536 + 1024 + h * 64 + 2 * cg;
                uh = *(const uint2*)(bHp + gw);
                ul = *(const uint2*)(bLp + gw);
            }
            vpre[i][0] = wh.x; vpre[i][1] = wh.y; vpre[i][2] = uh.x; vpre[i][3] = uh.y;
            vpre[i][4] = wl.x; vpre[i][5] = wl.y; vpre[i][6] = ul.x; vpre[i][7] = ul.y;
        }
    };

    auto stsV = [&](int p) {
        unsigned* VHp = VH + p * ATT_PW;
        unsigned* VLp = VL + p * ATT_PW;
#pragma unroll
        for (int i = 0; i < 8; i++) {
            int idx = i * 128 + t;
            int kp = idx >> 5;
            int cg = idx & 31;
            int wb = kp * 136 + 4 * cg;
            VHp[wb + 0] = __byte_perm(vpre[i][0], vpre[i][2], 0x5410);
            VHp[wb + 1] = __byte_perm(vpre[i][0], vpre[i][2], 0x7632);
            VHp[wb + 2] = __byte_perm(vpre[i][1], vpre[i][3], 0x5410);
            VHp[wb + 3] = __byte_perm(vpre[i][1], vpre[i][3], 0x7632);
            VLp[wb + 0] = __byte_perm(vpre[i][4], vpre[i][6], 0x5410);
            VLp[wb + 1] = __byte_perm(vpre[i][4], vpre[i][6], 0x7632);
            VLp[wb + 2] = __byte_perm(vpre[i][5], vpre[i][7], 0x5410);
            VLp[wb + 3] = __byte_perm(vpre[i][5], vpre[i][7], 0x7632);
        }
    };

    stageK(0, 0);
    loadV(0);
#pragma unroll
    for (int i = 0; i < 8; i++) {
        int idx = i * 128 + t;
        int row = idx >> 4;
        int c4w = (idx & 15) * 4;
        int grow = qt * 64 + row;
        uint4 vh = make_uint4(0,0,0,0), vl = make_uint4(0,0,0,0);
        if (grow < NTOK) {
            size_t gw = (size_t)grow * 1536 + h * 64 + c4w;
            vh = *(const uint4*)(bHp + gw);
            vl = *(const uint4*)(bLp + gw);
        }
        *(uint4*)(QH + row * 68 + c4w) = vh;
        *(uint4*)(QL + row * 68 + c4w) = vl;
    }
    stsV(0);
    cp_wait<0>();
    __syncthreads();

    float o[16][4];
#pragma unroll
    for (int ni = 0; ni < 16; ni++)
#pragma unroll
        for (int e = 0; e < 4; e++) o[ni][e] = 0.f;
    float mrow[2] = {-1e30f, -1e30f};
    float lrow[2] = {0.f, 0.f};

    for (int jt = 0; jt <= qt; jt++) {
        const int p = jt & 1;
        const bool more = jt < qt;
        if (more) {
            stageK(jt + 1, p ^ 1);
            loadV(jt + 1);
        }

        const unsigned* KHp = KH + p * ATT_PW;
        const unsigned* KLp = KL + p * ATT_PW;
        const unsigned* VHp = VH + p * ATT_PW;
        const unsigned* VLp = VL + p * ATT_PW;

        float s[8][4];
#pragma unroll
        for (int ni = 0; ni < 8; ni++)
#pragma unroll
            for (int e = 0; e < 4; e++) s[ni][e] = 0.f;

        const int r0 = w * 16 + g;
#pragma unroll
        for (int ko = 0; ko < 8; ko++) {
            unsigned qh[4], ql[4];
            int w0 = r0 * 68 + q + ko * 8;
            int w1 = (r0 + 8) * 68 + q + ko * 8;
            qh[0] = QH[w0];     qh[1] = QH[w1];
            qh[2] = QH[w0 + 4]; qh[3] = QH[w1 + 4];
            ql[0] = QL[w0];     ql[1] = QL[w1];
            ql[2] = QL[w0 + 4]; ql[3] = QL[w1 + 4];
#pragma unroll
            for (int ni = 0; ni < 8; ni++) {
                int nb = ni * 8 + g;
                unsigned bhf[2], blf[2];
                bhf[0] = KHp[nb * 68 + q + ko * 8];
                bhf[1] = KHp[nb * 68 + q + 4 + ko * 8];
                blf[0] = KLp[nb * 68 + q + ko * 8];
                blf[1] = KLp[nb * 68 + q + 4 + ko * 8];
                mma_bf16(s[ni], qh, bhf);
                mma_bf16(s[ni], qh, blf);
                mma_bf16(s[ni], ql, bhf);
            }
        }

#pragma unroll
        for (int ni = 0; ni < 8; ni++)
#pragma unroll
            for (int e = 0; e < 4; e++) s[ni][e] *= scale;

        if (jt == qt) {
            int rbase = qt * 64 + w * 16 + g;
#pragma unroll
            for (int ni = 0; ni < 8; ni++) {
                int cbase = jt * 64 + ni * 8 + 2 * q;
#pragma unroll
                for (int e = 0; e < 4; e++) {
                    int row = rbase + (e >= 2 ? 8 : 0);
                    int col = cbase + (e & 1);
                    if (col > row) s[ni][e] = -1e30f;
                }
            }
        }

        float mt[2] = {-1e30f, -1e30f};
#pragma unroll
        for (int ni = 0; ni < 8; ni++) {
            mt[0] = fmaxf(mt[0], fmaxf(s[ni][0], s[ni][1]));
            mt[1] = fmaxf(mt[1], fmaxf(s[ni][2], s[ni][3]));
        }
#pragma unroll
        for (int d = 1; d <= 2; d <<= 1) {
            mt[0] = fmaxf(mt[0], __shfl_xor_sync(0xFFFFFFFFu, mt[0], d));
            mt[1] = fmaxf(mt[1], __shfl_xor_sync(0xFFFFFFFFu, mt[1], d));
        }
        float mn[2] = {fmaxf(mrow[0], mt[0]), fmaxf(mrow[1], mt[1])};
        float corr[2] = {__expf(mrow[0] - mn[0]), __expf(mrow[1] - mn[1])};

        float rs[2] = {0.f, 0.f};
#pragma unroll
        for (int ni = 0; ni < 8; ni++) {
#pragma unroll
            for (int e = 0; e < 4; e++) {
                float pv = __expf(s[ni][e] - mn[e >> 1]);
                s[ni][e] = pv;
                rs[e >> 1] += pv;
            }
        }
#pragma unroll
        for (int d = 1; d <= 2; d <<= 1) {
            rs[0] += __shfl_xor_sync(0xFFFFFFFFu, rs[0], d);
            rs[1] += __shfl_xor_sync(0xFFFFFFFFu, rs[1], d);
        }
        lrow[0] = lrow[0] * corr[0] + rs[0];
        lrow[1] = lrow[1] * corr[1] + rs[1];
        mrow[0] = mn[0];
        mrow[1] = mn[1];
#pragma unroll
        for (int ni = 0; ni < 16; ni++) {
            o[ni][0] *= corr[0]; o[ni][1] *= corr[0];
            o[ni][2] *= corr[1]; o[ni][3] *= corr[1];
        }

#pragma unroll
        for (int kp = 0; kp < 4; kp++) {
            unsigned ph[4], pl[4];
            split_pair(s[2*kp][0],   s[2*kp][1],   ph[0], pl[0]);
            split_pair(s[2*kp][2],   s[2*kp][3],   ph[1], pl[1]);
            split_pair(s[2*kp+1][0], s[2*kp+1][1], ph[2], pl[2]);
            split_pair(s[2*kp+1][2], s[2*kp+1][3], ph[3], pl[3]);
#pragma unroll
            for (int ni = 0; ni < 16; ni++) {
                int nb = ni * 8 + g;
                unsigned bhf[2], blf[2];
                bhf[0] = VHp[(q + kp * 8) * 136 + nb];
                bhf[1] = VHp[(q + 4 + kp * 8) * 136 + nb];
                blf[0] = VLp[(q + kp * 8) * 136 + nb];
                blf[1] = VLp[(q + 4 + kp * 8) * 136 + nb];
                mma_bf16(o[ni], ph, bhf);
                mma_bf16(o[ni], ph, blf);
                mma_bf16(o[ni], pl, bhf);
            }
        }

        if (more) {
            stsV(p ^ 1);
            cp_wait<0>();
        }
        __syncthreads();
    }

    float inv[2] = {1.f / lrow[0], 1.f / lrow[1]};
    int rbase = qt * 64 + w * 16 + g;
#pragma unroll
    for (int ni = 0; ni < 16; ni++) {
        int cb = h * DHEAD + ni * 8 + 2 * q;
#pragma unroll
        for (int half = 0; half < 2; half++) {
            int row = rbase + half * 8;
            if (row >= NTOK) continue;
            unsigned hw, lw;
            split_pair(o[ni][half*2] * inv[half], o[ni][half*2+1] * inv[half], hw, lw);
            size_t wi = (size_t)(b * NTOK + row) * (DIMM / 2) + (cb >> 1);
            OH[wi] = hw;
            OL[wi] = lw;
        }
    }
}

// ---------------- small kernels ----------------
__global__ void save_cls_kernel(const float* __restrict__ gx, float* __restrict__ gcls)
{
    int idx = blockIdx.x * blockDim.x + threadIdx.x;
    if (idx >= BATCH * DIMM) return;
    int b = idx / DIMM, d = idx % DIMM;
    gcls[idx] = gx[((size_t)b * NTOK) * DIMM + d];
}

__global__ void write_out_kernel(const float* __restrict__ gx,
                                 const float* __restrict__ gcls,
                                 float* __restrict__ out)
{
    const int totalx = MROWS * DIMM;
    const int totalc = BATCH * DIMM;
    int idx = blockIdx.x * blockDim.x + threadIdx.x;
    if (idx < totalx)               out[idx] = gx[idx];
    else if (idx < totalx + totalc) out[idx] = gcls[idx - totalx];
}

// ---------------- host orchestration ----------------
struct DevPtrs {
    float *gx, *gcls;
    unsigned *xsh, *xsl, *ash, *asl, *hsh, *hsl, *qsh, *qsl;
    unsigned *wqh, *wql, *woh, *wol, *w1h, *w1l, *w2h, *w2l;
};

static void run_layer(int l, const DevPtrs& P,
                      const float* bo, const float* b1, const float* b2)
{
    const int gy = (MROWS + 127) / 128;  // 33
    tgemm_kernel<false,false,false,false,true><<<dim3(24, gy), 128, SM_TOTAL>>>(
        P.xsh, P.xsl, P.wqh + (size_t)l*WQKV_L, P.wql + (size_t)l*WQKV_L,
        nullptr, nullptr, nullptr, P.qsh, P.qsl, MROWS, DIMM, 3*DIMM);
    fattn_kernel<<<dim3(33, BATCH*NHEADS), 128, ATT_SMEM>>>(P.qsh, P.qsl, P.ash, P.asl);
    tgemm_kernel<true,true,false,true,true><<<dim3(8, gy), 128, SM_TOTAL>>>(
        P.ash, P.asl, P.woh + (size_t)l*WO_L, P.wol + (size_t)l*WO_L,
        bo, P.gx, P.gx, P.xsh, P.xsl, MROWS, DIMM, DIMM);
    tgemm_kernel<true,false,true,false,true><<<dim3(32, gy), 128, SM_TOTAL>>>(
        P.xsh, P.xsl, P.w1h + (size_t)l*W1_L, P.w1l + (size_t)l*W1_L,
        b1, nullptr, nullptr, P.hsh, P.hsl, MROWS, DIMM, HID);
    tgemm_kernel<true,true,false,true,true><<<dim3(8, gy), 128, SM_TOTAL>>>(
        P.hsh, P.hsl, P.w2h + (size_t)l*W2_L, P.w2l + (size_t)l*W2_L,
        b2, P.gx, P.gx, P.xsh, P.xsl, MROWS, HID, DIMM);
}

extern "C" void kernel_launch(void* const* d_in, const int* in_sizes, int n_in,
                              void* d_out, int out_size)
{
    const float* x_in = (const float*)d_in[0];
    const float* cls  = (const float*)d_in[1];
    const float* hW[7];
    const float* tW[7];
    for (int i = 0; i < 7; i++) hW[i] = (const float*)d_in[2 + i];
    for (int i = 0; i < 7; i++) tW[i] = (const float*)d_in[9 + i];

    cudaFuncSetAttribute(tgemm_kernel<false,false,false,false,true>,
                         cudaFuncAttributeMaxDynamicSharedMemorySize, SM_TOTAL);
    cudaFuncSetAttribute(tgemm_kernel<true,true,false,true,true>,
                         cudaFuncAttributeMaxDynamicSharedMemorySize, SM_TOTAL);
    cudaFuncSetAttribute(tgemm_kernel<true,false,true,false,true>,
                         cudaFuncAttributeMaxDynamicSharedMemorySize, SM_TOTAL);
    cudaFuncSetAttribute(fattn_kernel,
                         cudaFuncAttributeMaxDynamicSharedMemorySize, ATT_SMEM);

    DevPtrs P;
    cudaGetSymbolAddress((void**)&P.gx,   g_x);
    cudaGetSymbolAddress((void**)&P.gcls, g_cls);
    cudaGetSymbolAddress((void**)&P.xsh,  g_xs_h);
    cudaGetSymbolAddress((void**)&P.xsl,  g_xs_l);
    cudaGetSymbolAddress((void**)&P.ash,  g_as_h);
    cudaGetSymbolAddress((void**)&P.asl,  g_as_l);
    cudaGetSymbolAddress((void**)&P.hsh,  g_hs_h);
    cudaGetSymbolAddress((void**)&P.hsl,  g_hs_l);
    cudaGetSymbolAddress((void**)&P.qsh,  g_qs_h);
    cudaGetSymbolAddress((void**)&P.qsl,  g_qs_l);
    cudaGetSymbolAddress((void**)&P.wqh,  g_wqkv_h);
    cudaGetSymbolAddress((void**)&P.wql,  g_wqkv_l);
    cudaGetSymbolAddress((void**)&P.woh,  g_wo_h);
    cudaGetSymbolAddress((void**)&P.wol,  g_wo_l);
    cudaGetSymbolAddress((void**)&P.w1h,  g_w1_h);
    cudaGetSymbolAddress((void**)&P.w1l,  g_w1_l);
    cudaGetSymbolAddress((void**)&P.w2h,  g_w2_h);
    cudaGetSymbolAddress((void**)&P.w2l,  g_w2_l);

    split_w2_kernel<<<dim3(3072/256, 1024/16, 8), 256>>>(hW[0], tW[0], P.wqh, P.wql, 1024, 3072);
    split_w2_kernel<<<dim3(1024/256, 1024/16, 8), 256>>>(hW[1], tW[1], P.woh, P.wol, 1024, 1024);
    split_w2_kernel<<<dim3(4096/256, 1024/16, 8), 256>>>(hW[3], tW[3], P.w1h, P.w1l, 1024, 4096);
    split_w2_kernel<<<dim3(1024/256, 4096/16, 8), 256>>>(hW[5], tW[5], P.w2h, P.w2l, 4096, 1024);

    {
        int total = MROWS * DIMM / 2;
        concat_kernel<<<(total + 255) / 256, 256>>>(x_in, cls, P.gx, P.xsh, P.xsl);
    }

    for (int l = 0; l < L_HEAD; l++)
        run_layer(l, P, hW[2] + (size_t)l*DIMM, hW[4] + (size_t)l*HID, hW[6] + (size_t)l*DIMM);

    save_cls_kernel<<<(BATCH*DIMM + 255)/256, 256>>>(P.gx, P.gcls);

    for (int l = 0; l < L_TAIL; l++)
        run_layer(4 + l, P, tW[2] + (size_t)l*DIMM, tW[4] + (size_t)l*HID, tW[6] + (size_t)l*DIMM);

    {
        int total = MROWS * DIMM + BATCH * DIMM;
        write_out_kernel<<<(total + 255)/256, 256>>>(P.gx, P.gcls, (float*)d_out);
    }
}

// round 16
// speedup vs baseline: 1.0364x; 1.0364x over previous
#include <cuda_runtime.h>
#include <cuda_bf16.h>
#include <math.h>
#include <stdint.h>

// ---------------- problem constants ----------------
#define DIMM   1024
#define NHEADS 8
#define DHEAD  128
#define NTOK   2049
#define BATCH  2
#define MROWS  (BATCH*NTOK)  // 4098
#define HID    4096
#define L_HEAD 4
#define L_TAIL 4

// ---------------- scratch (device globals) ----------------
__device__ __align__(16) float g_x  [(size_t)MROWS*DIMM];
__device__ __align__(16) float g_cls[(size_t)BATCH*DIMM];

__device__ __align__(16) unsigned g_xs_h[(size_t)MROWS*DIMM/2];
__device__ __align__(16) unsigned g_xs_l[(size_t)MROWS*DIMM/2];
__device__ __align__(16) unsigned g_as_h[(size_t)MROWS*DIMM/2];
__device__ __align__(16) unsigned g_as_l[(size_t)MROWS*DIMM/2];
__device__ __align__(16) unsigned g_hs_h[(size_t)MROWS*HID/2];
__device__ __align__(16) unsigned g_hs_l[(size_t)MROWS*HID/2];
__device__ __align__(16) unsigned g_qs_h[(size_t)MROWS*3*DIMM/2];
__device__ __align__(16) unsigned g_qs_l[(size_t)MROWS*3*DIMM/2];

// weight splits, frag-pair layout:
//   word offset (per layer) = (g8*N + n)*8 + q*2 + h,  k2 = 8*g8 + q + 4*h
#define WQKV_L (512*3072)
#define WO_L   (512*1024)
#define W1_L   (512*4096)
#define W2_L   (2048*1024)
__device__ __align__(16) unsigned g_wqkv_h[8*(size_t)WQKV_L];
__device__ __align__(16) unsigned g_wqkv_l[8*(size_t)WQKV_L];
__device__ __align__(16) unsigned g_wo_h[8*(size_t)WO_L];
__device__ __align__(16) unsigned g_wo_l[8*(size_t)WO_L];
__device__ __align__(16) unsigned g_w1_h[8*(size_t)W1_L];
__device__ __align__(16) unsigned g_w1_l[8*(size_t)W1_L];
__device__ __align__(16) unsigned g_w2_h[8*(size_t)W2_L];
__device__ __align__(16) unsigned g_w2_l[8*(size_t)W2_L];

// ---------------- bf16 helpers ----------------
__device__ __forceinline__ unsigned short f2bf(float x) {
    __nv_bfloat16 h = __float2bfloat16(x);
    return *reinterpret_cast<unsigned short*>(&h);
}
__device__ __forceinline__ float bf2f(unsigned short s) {
    __nv_bfloat16 h = *reinterpret_cast<__nv_bfloat16*>(&s);
    return __bfloat162float(h);
}
__device__ __forceinline__ void split_bf16(float x, unsigned short& hi, unsigned short& lo) {
    hi = f2bf(x);
    lo = f2bf(x - bf2f(hi));
}
__device__ __forceinline__ void split_pair(float a, float b, unsigned& hw, unsigned& lw) {
    unsigned short ah, al, bh, bl;
    split_bf16(a, ah, al);
    split_bf16(b, bh, bl);
    hw = (unsigned)ah | ((unsigned)bh << 16);
    lw = (unsigned)al | ((unsigned)bl << 16);
}

__device__ __forceinline__ void mma_bf16(float* c, const unsigned* a, const unsigned* b) {
    asm("mma.sync.aligned.m16n8k16.row.col.f32.bf16.bf16.f32 "
        "{%0,%1,%2,%3}, {%4,%5,%6,%7}, {%8,%9}, {%0,%1,%2,%3};"
        : "+f"(c[0]), "+f"(c[1]), "+f"(c[2]), "+f"(c[3])
        : "r"(a[0]), "r"(a[1]), "r"(a[2]), "r"(a[3]),
          "r"(b[0]), "r"(b[1]));
}

__device__ __forceinline__ void ldsm4(unsigned* r, const void* p) {
    unsigned a = (unsigned)__cvta_generic_to_shared(p);
    asm volatile("ldmatrix.sync.aligned.m8n8.x4.shared.b16 {%0,%1,%2,%3}, [%4];"
        : "=r"(r[0]), "=r"(r[1]), "=r"(r[2]), "=r"(r[3]) : "r"(a));
}

__device__ __forceinline__ void cpa16(void* dst, const void* src, int sz) {
    unsigned d = (unsigned)__cvta_generic_to_shared(dst);
    asm volatile("cp.async.cg.shared.global [%0], [%1], 16, %2;" :: "r"(d), "l"(src), "r"(sz));
}
__device__ __forceinline__ void cp_commit() { asm volatile("cp.async.commit_group;"); }
template<int N> __device__ __forceinline__ void cp_wait() {
    asm volatile("cp.async.wait_group %0;" :: "n"(N));
}

// ---------------- weight pre-split kernel (frag-pair layout, tiled/coalesced) ----------
__global__ void split_w2_kernel(const float* __restrict__ Wh, const float* __restrict__ Wt,
                                unsigned* __restrict__ oH, unsigned* __restrict__ oL,
                                int K, int N)
{
    __shared__ unsigned smh[8][257], sml[8][257];
    int l = blockIdx.z;
    const float* W = (l < 4) ? (Wh + (size_t)l * K * N) : (Wt + (size_t)(l - 4) * K * N);
    int g8 = blockIdx.y;
    int n0 = blockIdx.x * 256;
    int tx = threadIdx.x;
#pragma unroll
    for (int r = 0; r < 8; r++) {
        int k2 = g8 * 8 + r;
        float a = W[(size_t)(2 * k2) * N + n0 + tx];
        float b = W[(size_t)(2 * k2 + 1) * N + n0 + tx];
        unsigned hw, lw;
        split_pair(a, b, hw, lw);
        smh[r][tx] = hw;
        sml[r][tx] = lw;
    }
    __syncthreads();
    size_t base = (size_t)l * ((size_t)K * N / 2) + ((size_t)g8 * N + n0 + tx) * 8;
    unsigned vh[8], vl[8];
#pragma unroll
    for (int j = 0; j < 8; j++) {
        int r = (j >> 1) + 4 * (j & 1);
        vh[j] = smh[r][tx];
        vl[j] = sml[r][tx];
    }
    *(uint4*)(oH + base)     = make_uint4(vh[0], vh[1], vh[2], vh[3]);
    *(uint4*)(oH + base + 4) = make_uint4(vh[4], vh[5], vh[6], vh[7]);
    *(uint4*)(oL + base)     = make_uint4(vl[0], vl[1], vl[2], vl[3]);
    *(uint4*)(oL + base + 4) = make_uint4(vl[4], vl[5], vl[6], vl[7]);
}

// ---------------- concat cls + x ----------------
__global__ void concat_kernel(const float* __restrict__ x, const float* __restrict__ cls,
                              float* __restrict__ gx,
                              unsigned* __restrict__ xh, unsigned* __restrict__ xl)
{
    int idx = blockIdx.x * blockDim.x + threadIdx.x;
    int total = MROWS * DIMM / 2;
    if (idx >= total) return;
    int c2  = idx % (DIMM / 2);
    int row = idx / (DIMM / 2);
    int n = row % NTOK, b = row / NTOK;
    float v0, v1;
    if (n == 0) { v0 = cls[c2 * 2]; v1 = cls[c2 * 2 + 1]; }
    else {
        const float* p = x + ((size_t)b * (NTOK - 1) + (n - 1)) * DIMM + c2 * 2;
        v0 = p[0]; v1 = p[1];
    }
    gx[idx * 2] = v0; gx[idx * 2 + 1] = v1;
    unsigned hw, lw;
    split_pair(v0, v1, hw, lw);
    xh[idx] = hw; xl[idx] = lw;
}

// ---------------- tensor-core GEMM: 8 warps 64x32, 3-stage early-issue, 2 CTAs/SM -------
#define AST_B 80
#define STG_A (128*AST_B)               // 10240 per A plane
#define BGRP  1032                      // words per k-group (1024 data + 8 pad)
#define STG_B4 (2*BGRP*4)               // 8256 bytes per B plane
#define STG_BYTES (2*STG_A + 2*STG_B4)  // 36992
#define NSTAGE 3
#define SM_TOTAL (NSTAGE*STG_BYTES)     // 110976

template<bool BIAS, bool RESID, bool DOGELU, bool W32, bool WS>
__global__ __launch_bounds__(256, 2)
void tgemm_kernel(const unsigned* __restrict__ AH, const unsigned* __restrict__ AL,
                  const unsigned* __restrict__ BH, const unsigned* __restrict__ BL,
                  const float* __restrict__ bias, const float* __restrict__ R,
                  float* __restrict__ C,
                  unsigned* __restrict__ OH, unsigned* __restrict__ OL,
                  int M, int K, int N)
{
    extern __shared__ char smem[];

    const int t    = threadIdx.x;
    const int warp = t >> 5;
    const int lane = t & 31;
    const int g    = lane >> 2;
    const int q    = lane & 3;
    const int wm   = warp & 1;
    const int wn   = warp >> 1;
    const int bm   = blockIdx.y * 128;
    const int bn   = blockIdx.x * 128;
    const int steps = K >> 5;

    float acc[4][4][4];
#pragma unroll
    for (int i = 0; i < 4; i++)
#pragma unroll
        for (int j = 0; j < 4; j++)
#pragma unroll
            for (int e = 0; e < 4; e++) acc[i][j][e] = 0.f;

    const int ar0 = t >> 2,  ac0 = (t & 3);
    const int ar1 = (t + 256) >> 2, ac1 = (t & 3);

    const unsigned short* AHg = (const unsigned short*)AH;
    const unsigned short* ALg = (const unsigned short*)AL;

    auto issue = [&](int s) {
        char* buf = smem + (s % NSTAGE) * STG_BYTES;
        char* AHs = buf;
        char* ALs = buf + STG_A;
        char* BHs = buf + 2 * STG_A;
        char* BLs = buf + 2 * STG_A + STG_B4;
        int k0 = s * 32;
        {
            int gr = bm + ar0;
            int sz = (gr < M) ? 16 : 0;
            size_t so = (size_t)(gr < M ? gr : 0) * K + k0 + ac0 * 8;
            cpa16(AHs + ar0 * AST_B + ac0 * 16, AHg + so, sz);
            cpa16(ALs + ar0 * AST_B + ac0 * 16, ALg + so, sz);
            gr = bm + ar1;
            sz = (gr < M) ? 16 : 0;
            so = (size_t)(gr < M ? gr : 0) * K + k0 + ac1 * 8;
            cpa16(AHs + ar1 * AST_B + ac1 * 16, AHg + so, sz);
            cpa16(ALs + ar1 * AST_B + ac1 * 16, ALg + so, sz);
        }
        {
            int sgrp = s * 2;
            size_t src0 = ((size_t)sgrp * N + bn) * 8 + t * 4;
            size_t src1 = ((size_t)(sgrp + 1) * N + bn) * 8 + t * 4;
            int d0 = t * 4;
            int d1 = BGRP + t * 4;
            cpa16(BHs + d0 * 4, BH + src0, 16);
            cpa16(BLs + d0 * 4, BL + src0, 16);
            cpa16(BHs + d1 * 4, BH + src1, 16);
            cpa16(BLs + d1 * 4, BL + src1, 16);
        }
        cp_commit();
    };

    issue(0);
    if (steps > 1) issue(1);

    const int lanebase = (wm * 64 + (lane & 7) + ((lane >> 3) & 1) * 8) * AST_B + (lane >> 4) * 16;

    for (int s = 0; s < steps; s++) {
        if (s + 1 < steps) cp_wait<1>();
        else               cp_wait<0>();
        __syncthreads();

        if (s + 2 < steps) issue(s + 2);

        const char* buf = smem + (s % NSTAGE) * STG_BYTES;
        const char* AHs = buf;
        const char* ALs = buf + STG_A;
        const unsigned* BHw = (const unsigned*)(buf + 2 * STG_A);
        const unsigned* BLw = (const unsigned*)(buf + 2 * STG_A + STG_B4);

#pragma unroll
        for (int ko = 0; ko < 2; ko++) {
            unsigned bh[4][2], bl[4][2];
#pragma unroll
            for (int ni = 0; ni < 4; ni++) {
                int ad = ko * BGRP + (wn * 32 + g + ni * 8) * 8 + q * 2;
                uint2 vh2 = *(const uint2*)(BHw + ad);
                uint2 vl2 = *(const uint2*)(BLw + ad);
                bh[ni][0] = vh2.x; bh[ni][1] = vh2.y;
                bl[ni][0] = vl2.x; bl[ni][1] = vl2.y;
            }
#pragma unroll
            for (int mi = 0; mi < 4; mi++) {
                unsigned ah[4], al[4];
                ldsm4(ah, AHs + lanebase + mi * (16 * AST_B) + ko * 32);
                ldsm4(al, ALs + lanebase + mi * (16 * AST_B) + ko * 32);
#pragma unroll
                for (int ni = 0; ni < 4; ni++) {
                    mma_bf16(acc[mi][ni], ah, bh[ni]);
                    mma_bf16(acc[mi][ni], ah, bl[ni]);
                    mma_bf16(acc[mi][ni], al, bh[ni]);
                }
            }
        }
    }

    // ---- epilogue (vectorized stores) ----
    const int Nw = N >> 1;
#pragma unroll
    for (int mi = 0; mi < 4; mi++) {
        int r0 = bm + wm * 64 + mi * 16 + g;
#pragma unroll
        for (int ni = 0; ni < 4; ni++) {
            int cb = bn + wn * 32 + ni * 8 + 2 * q;
            float v[4];
#pragma unroll
            for (int e = 0; e < 4; e++) {
                v[e] = acc[mi][ni][e];
                if (BIAS) v[e] += bias[cb + (e & 1)];
                if (DOGELU) v[e] = 0.5f * v[e] * (1.f + erff(v[e] * 0.70710678118f));
            }
#pragma unroll
            for (int half = 0; half < 2; half++) {
                int gr = r0 + half * 8;
                if (gr >= M) continue;
                float a = v[half * 2], b = v[half * 2 + 1];
                if (RESID) {
                    float2 r2 = *(const float2*)(R + (size_t)gr * N + cb);
                    a += r2.x;
                    b += r2.y;
                }
                if (W32) {
                    *(float2*)(C + (size_t)gr * N + cb) = make_float2(a, b);
                }
                if (WS) {
                    unsigned hw, lw;
                    split_pair(a, b, hw, lw);
                    size_t wi = (size_t)gr * Nw + (cb >> 1);
                    OH[wi] = hw;
                    OL[wi] = lw;
                }
            }
        }
    }
}

// ---------------- flash attention: double-buffered K (cp.async) + V (reg prefetch) -------
#define ATT_PW 4352
#define ATT_SMEM (10*ATT_PW*4)   // 174080 bytes

__global__ __launch_bounds__(128, 1)
void fattn_kernel(const unsigned* __restrict__ QVH, const unsigned* __restrict__ QVL,
                  unsigned* __restrict__ OH, unsigned* __restrict__ OL)
{
    extern __shared__ unsigned smw[];
    unsigned* QH = smw;
    unsigned* QL = QH + ATT_PW;
    unsigned* KH = QL + ATT_PW;
    unsigned* KL = KH + 2*ATT_PW;
    unsigned* VH = KL + 2*ATT_PW;
    unsigned* VL = VH + 2*ATT_PW;

    const int t    = threadIdx.x;
    const int lane = t & 31;
    const int w    = t >> 5;
    const int g    = lane >> 2;
    const int q    = lane & 3;
    const int qt   = 32 - blockIdx.x;
    const int bh   = blockIdx.y;
    const int h    = bh & 7;
    const int b    = bh >> 3;
    const float scale = 0.03125f;

    const unsigned* bHp = QVH + (size_t)b * NTOK * 1536;
    const unsigned* bLp = QVL + (size_t)b * NTOK * 1536;

    unsigned vpre[8][8];

    auto stageK = [&](int jt, int p) {
        unsigned* KHp = KH + p * ATT_PW;
        unsigned* KLp = KL + p * ATT_PW;
#pragma unroll
        for (int i = 0; i < 8; i++) {
            int idx = i * 128 + t;
            int key = idx >> 4;
            int c4w = (idx & 15) * 4;
            int gkey = jt * 64 + key;
            int sz = (gkey < NTOK) ? 16 : 0;
            size_t gw = (size_t)(gkey < NTOK ? gkey : 0) * 1536 + 512 + h * 64 + c4w;
            cpa16(KHp + key * 68 + c4w, bHp + gw, sz);
            cpa16(KLp + key * 68 + c4w, bLp + gw, sz);
        }
        cp_commit();
    };

    auto loadV = [&](int jt) {
#pragma unroll
        for (int i = 0; i < 8; i++) {
            int idx = i * 128 + t;
            int kp = idx >> 5;
            int cg = idx & 31;
            int k0g = jt * 64 + 2 * kp;
            uint2 wh = make_uint2(0,0), uh = make_uint2(0,0);
            uint2 wl = make_uint2(0,0), ul = make_uint2(0,0);
            if (k0g < NTOK) {
                size_t gw = (size_t)k0g * 1536 + 1024 + h * 64 + 2 * cg;
                wh = *(const uint2*)(bHp + gw);
                wl = *(const uint2*)(bLp + gw);
            }
            if (k0g + 1 < NTOK) {
                size_t gw = (size_t)(k0g + 1) * 1536 + 1024 + h * 64 + 2 * cg;
                uh = *(const uint2*)(bHp + gw);
                ul = *(const uint2*)(bLp + gw);
            }
            vpre[i][0] = wh.x; vpre[i][1] = wh.y; vpre[i][2] = uh.x; vpre[i][3] = uh.y;
            vpre[i][4] = wl.x; vpre[i][5] = wl.y; vpre[i][6] = ul.x; vpre[i][7] = ul.y;
        }
    };

    auto stsV = [&](int p) {
        unsigned* VHp = VH + p * ATT_PW;
        unsigned* VLp = VL + p * ATT_PW;
#pragma unroll
        for (int i = 0; i < 8; i++) {
            int idx = i * 128 + t;
            int kp = idx >> 5;
            int cg = idx & 31;
            int wb = kp * 136 + 4 * cg;
            VHp[wb + 0] = __byte_perm(vpre[i][0], vpre[i][2], 0x5410);
            VHp[wb + 1] = __byte_perm(vpre[i][0], vpre[i][2], 0x7632);
            VHp[wb + 2] = __byte_perm(vpre[i][1], vpre[i][3], 0x5410);
            VHp[wb + 3] = __byte_perm(vpre[i][1], vpre[i][3], 0x7632);
            VLp[wb + 0] = __byte_perm(vpre[i][4], vpre[i][6], 0x5410);
            VLp[wb + 1] = __byte_perm(vpre[i][4], vpre[i][6], 0x7632);
            VLp[wb + 2] = __byte_perm(vpre[i][5], vpre[i][7], 0x5410);
            VLp[wb + 3] = __byte_perm(vpre[i][5], vpre[i][7], 0x7632);
        }
    };

    stageK(0, 0);
    loadV(0);
#pragma unroll
    for (int i = 0; i < 8; i++) {
        int idx = i * 128 + t;
        int row = idx >> 4;
        int c4w = (idx & 15) * 4;
        int grow = qt * 64 + row;
        uint4 vh = make_uint4(0,0,0,0), vl = make_uint4(0,0,0,0);
        if (grow < NTOK) {
            size_t gw = (size_t)grow * 1536 + h * 64 + c4w;
            vh = *(const uint4*)(bHp + gw);
            vl = *(const uint4*)(bLp + gw);
        }
        *(uint4*)(QH + row * 68 + c4w) = vh;
        *(uint4*)(QL + row * 68 + c4w) = vl;
    }
    stsV(0);
    cp_wait<0>();
    __syncthreads();

    float o[16][4];
#pragma unroll
    for (int ni = 0; ni < 16; ni++)
#pragma unroll
        for (int e = 0; e < 4; e++) o[ni][e] = 0.f;
    float mrow[2] = {-1e30f, -1e30f};
    float lrow[2] = {0.f, 0.f};

    for (int jt = 0; jt <= qt; jt++) {
        const int p = jt & 1;
        const bool more = jt < qt;
        if (more) {
            stageK(jt + 1, p ^ 1);
            loadV(jt + 1);
        }

        const unsigned* KHp = KH + p * ATT_PW;
        const unsigned* KLp = KL + p * ATT_PW;
        const unsigned* VHp = VH + p * ATT_PW;
        const unsigned* VLp = VL + p * ATT_PW;

        float s[8][4];
#pragma unroll
        for (int ni = 0; ni < 8; ni++)
#pragma unroll
            for (int e = 0; e < 4; e++) s[ni][e] = 0.f;

        const int r0 = w * 16 + g;
#pragma unroll
        for (int ko = 0; ko < 8; ko++) {
            unsigned qh[4], ql[4];
            int w0 = r0 * 68 + q + ko * 8;
            int w1 = (r0 + 8) * 68 + q + ko * 8;
            qh[0] = QH[w0];     qh[1] = QH[w1];
            qh[2] = QH[w0 + 4]; qh[3] = QH[w1 + 4];
            ql[0] = QL[w0];     ql[1] = QL[w1];
            ql[2] = QL[w0 + 4]; ql[3] = QL[w1 + 4];
#pragma unroll
            for (int ni = 0; ni < 8; ni++) {
                int nb = ni * 8 + g;
                unsigned bhf[2], blf[2];
                bhf[0] = KHp[nb * 68 + q + ko * 8];
                bhf[1] = KHp[nb * 68 + q + 4 + ko * 8];
                blf[0] = KLp[nb * 68 + q + ko * 8];
                blf[1] = KLp[nb * 68 + q + 4 + ko * 8];
                mma_bf16(s[ni], qh, bhf);
                mma_bf16(s[ni], qh, blf);
                mma_bf16(s[ni], ql, bhf);
            }
        }

#pragma unroll
        for (int ni = 0; ni < 8; ni++)
#pragma unroll
            for (int e = 0; e < 4; e++) s[ni][e] *= scale;

        if (jt == qt) {
            int rbase = qt * 64 + w * 16 + g;
#pragma unroll
            for (int ni = 0; ni < 8; ni++) {
                int cbase = jt * 64 + ni * 8 + 2 * q;
#pragma unroll
                for (int e = 0; e < 4; e++) {
                    int row = rbase + (e >= 2 ? 8 : 0);
                    int col = cbase + (e & 1);
                    if (col > row) s[ni][e] = -1e30f;
                }
            }
        }

        float mt[2] = {-1e30f, -1e30f};
#pragma unroll
        for (int ni = 0; ni < 8; ni++) {
            mt[0] = fmaxf(mt[0], fmaxf(s[ni][0], s[ni][1]));
            mt[1] = fmaxf(mt[1], fmaxf(s[ni][2], s[ni][3]));
        }
#pragma unroll
        for (int d = 1; d <= 2; d <<= 1) {
            mt[0] = fmaxf(mt[0], __shfl_xor_sync(0xFFFFFFFFu, mt[0], d));
            mt[1] = fmaxf(mt[1], __shfl_xor_sync(0xFFFFFFFFu, mt[1], d));
        }
        float mn[2] = {fmaxf(mrow[0], mt[0]), fmaxf(mrow[1], mt[1])};
        float corr[2] = {__expf(mrow[0] - mn[0]), __expf(mrow[1] - mn[1])};

        float rs[2] = {0.f, 0.f};
#pragma unroll
        for (int ni = 0; ni < 8; ni++) {
#pragma unroll
            for (int e = 0; e < 4; e++) {
                float pv = __expf(s[ni][e] - mn[e >> 1]);
                s[ni][e] = pv;
                rs[e >> 1] += pv;
            }
        }
#pragma unroll
        for (int d = 1; d <= 2; d <<= 1) {
            rs[0] += __shfl_xor_sync(0xFFFFFFFFu, rs[0], d);
            rs[1] += __shfl_xor_sync(0xFFFFFFFFu, rs[1], d);
        }
        lrow[0] = lrow[0] * corr[0] + rs[0];
        lrow[1] = lrow[1] * corr[1] + rs[1];
        mrow[0] = mn[0];
        mrow[1] = mn[1];
#pragma unroll
        for (int ni = 0; ni < 16; ni++) {
            o[ni][0] *= corr[0]; o[ni][1] *= corr[0];
            o[ni][2] *= corr[1]; o[ni][3] *= corr[1];
        }

#pragma unroll
        for (int kp = 0; kp < 4; kp++) {
            unsigned ph[4], pl[4];
            split_pair(s[2*kp][0],   s[2*kp][1],   ph[0], pl[0]);
            split_pair(s[2*kp][2],   s[2*kp][3],   ph[1], pl[1]);
            split_pair(s[2*kp+1][0], s[2*kp+1][1], ph[2], pl[2]);
            split_pair(s[2*kp+1][2], s[2*kp+1][3], ph[3], pl[3]);
#pragma unroll
            for (int ni = 0; ni < 16; ni++) {
                int nb = ni * 8 + g;
                unsigned bhf[2], blf[2];
                bhf[0] = VHp[(q + kp * 8) * 136 + nb];
                bhf[1] = VHp[(q + 4 + kp * 8) * 136 + nb];
                blf[0] = VLp[(q + kp * 8) * 136 + nb];
                blf[1] = VLp[(q + 4 + kp * 8) * 136 + nb];
                mma_bf16(o[ni], ph, bhf);
                mma_bf16(o[ni], ph, blf);
                mma_bf16(o[ni], pl, bhf);
            }
        }

        if (more) {
            stsV(p ^ 1);
            cp_wait<0>();
        }
        __syncthreads();
    }

    float inv[2] = {1.f / lrow[0], 1.f / lrow[1]};
    int rbase = qt * 64 + w * 16 + g;
#pragma unroll
    for (int ni = 0; ni < 16; ni++) {
        int cb = h * DHEAD + ni * 8 + 2 * q;
#pragma unroll
        for (int half = 0; half < 2; half++) {
            int row = rbase + half * 8;
            if (row >= NTOK) continue;
            unsigned hw, lw;
            split_pair(o[ni][half*2] * inv[half], o[ni][half*2+1] * inv[half], hw, lw);
            size_t wi = (size_t)(b * NTOK + row) * (DIMM / 2) + (cb >> 1);
            OH[wi] = hw;
            OL[wi] = lw;
        }
    }
}

// ---------------- small kernels ----------------
__global__ void save_cls_kernel(const float* __restrict__ gx, float* __restrict__ gcls)
{
    int idx = blockIdx.x * blockDim.x + threadIdx.x;
    if (idx >= BATCH * DIMM) return;
    int b = idx / DIMM, d = idx % DIMM;
    gcls[idx] = gx[((size_t)b * NTOK) * DIMM + d];
}

__global__ void write_out_kernel(const float* __restrict__ gx,
                                 const float* __restrict__ gcls,
                                 float* __restrict__ out)
{
    const int totalx = MROWS * DIMM;
    const int totalc = BATCH * DIMM;
    int idx = blockIdx.x * blockDim.x + threadIdx.x;
    if (idx < totalx)               out[idx] = gx[idx];
    else if (idx < totalx + totalc) out[idx] = gcls[idx - totalx];
}

// ---------------- host orchestration ----------------
struct DevPtrs {
    float *gx, *gcls;
    unsigned *xsh, *xsl, *ash, *asl, *hsh, *hsl, *qsh, *qsl;
    unsigned *wqh, *wql, *woh, *wol, *w1h, *w1l, *w2h, *w2l;
};

static void run_layer(int l, const DevPtrs& P,
                      const float* bo, const float* b1, const float* b2)
{
    const int gy = (MROWS + 127) / 128;  // 33
    tgemm_kernel<false,false,false,false,true><<<dim3(24, gy), 256, SM_TOTAL>>>(
        P.xsh, P.xsl, P.wqh + (size_t)l*WQKV_L, P.wql + (size_t)l*WQKV_L,
        nullptr, nullptr, nullptr, P.qsh, P.qsl, MROWS, DIMM, 3*DIMM);
    fattn_kernel<<<dim3(33, BATCH*NHEADS), 128, ATT_SMEM>>>(P.qsh, P.qsl, P.ash, P.asl);
    tgemm_kernel<true,true,false,true,true><<<dim3(8, gy), 256, SM_TOTAL>>>(
        P.ash, P.asl, P.woh + (size_t)l*WO_L, P.wol + (size_t)l*WO_L,
        bo, P.gx, P.gx, P.xsh, P.xsl, MROWS, DIMM, DIMM);
    tgemm_kernel<true,false,true,false,true><<<dim3(32, gy), 256, SM_TOTAL>>>(
        P.xsh, P.xsl, P.w1h + (size_t)l*W1_L, P.w1l + (size_t)l*W1_L,
        b1, nullptr, nullptr, P.hsh, P.hsl, MROWS, DIMM, HID);
    tgemm_kernel<true,true,false,true,true><<<dim3(8, gy), 256, SM_TOTAL>>>(
        P.hsh, P.hsl, P.w2h + (size_t)l*W2_L, P.w2l + (size_t)l*W2_L,
        b2, P.gx, P.gx, P.xsh, P.xsl, MROWS, HID, DIMM);
}

extern "C" void kernel_launch(void* const* d_in, const int* in_sizes, int n_in,
                              void* d_out, int out_size)
{
    const float* x_in = (const float*)d_in[0];
    const float* cls  = (const float*)d_in[1];
    const float* hW[7];
    const float* tW[7];
    for (int i = 0; i < 7; i++) hW[i] = (const float*)d_in[2 + i];
    for (int i = 0; i < 7; i++) tW[i] = (const float*)d_in[9 + i];

    cudaFuncSetAttribute(tgemm_kernel<false,false,false,false,true>,
                         cudaFuncAttributeMaxDynamicSharedMemorySize, SM_TOTAL);
    cudaFuncSetAttribute(tgemm_kernel<true,true,false,true,true>,
                         cudaFuncAttributeMaxDynamicSharedMemorySize, SM_TOTAL);
    cudaFuncSetAttribute(tgemm_kernel<true,false,true,false,true>,
                         cudaFuncAttributeMaxDynamicSharedMemorySize, SM_TOTAL);
    cudaFuncSetAttribute(fattn_kernel,
                         cudaFuncAttributeMaxDynamicSharedMemorySize, ATT_SMEM);

    DevPtrs P;
    cudaGetSymbolAddress((void**)&P.gx,   g_x);
    cudaGetSymbolAddress((void**)&P.gcls, g_cls);
    cudaGetSymbolAddress((void**)&P.xsh,  g_xs_h);
    cudaGetSymbolAddress((void**)&P.xsl,  g_xs_l);
    cudaGetSymbolAddress((void**)&P.ash,  g_as_h);
    cudaGetSymbolAddress((void**)&P.asl,  g_as_l);
    cudaGetSymbolAddress((void**)&P.hsh,  g_hs_h);
    cudaGetSymbolAddress((void**)&P.hsl,  g_hs_l);
    cudaGetSymbolAddress((void**)&P.qsh,  g_qs_h);
    cudaGetSymbolAddress((void**)&P.qsl,  g_qs_l);
    cudaGetSymbolAddress((void**)&P.wqh,  g_wqkv_h);
    cudaGetSymbolAddress((void**)&P.wql,  g_wqkv_l);
    cudaGetSymbolAddress((void**)&P.woh,  g_wo_h);
    cudaGetSymbolAddress((void**)&P.wol,  g_wo_l);
    cudaGetSymbolAddress((void**)&P.w1h,  g_w1_h);
    cudaGetSymbolAddress((void**)&P.w1l,  g_w1_l);
    cudaGetSymbolAddress((void**)&P.w2h,  g_w2_h);
    cudaGetSymbolAddress((void**)&P.w2l,  g_w2_l);

    split_w2_kernel<<<dim3(3072/256, 1024/16, 8), 256>>>(hW[0], tW[0], P.wqh, P.wql, 1024, 3072);
    split_w2_kernel<<<dim3(1024/256, 1024/16, 8), 256>>>(hW[1], tW[1], P.woh, P.wol, 1024, 1024);
    split_w2_kernel<<<dim3(4096/256, 1024/16, 8), 256>>>(hW[3], tW[3], P.w1h, P.w1l, 1024, 4096);
    split_w2_kernel<<<dim3(1024/256, 4096/16, 8), 256>>>(hW[5], tW[5], P.w2h, P.w2l, 4096, 1024);

    {
        int total = MROWS * DIMM / 2;
        concat_kernel<<<(total + 255) / 256, 256>>>(x_in, cls, P.gx, P.xsh, P.xsl);
    }

    for (int l = 0; l < L_HEAD; l++)
        run_layer(l, P, hW[2] + (size_t)l*DIMM, hW[4] + (size_t)l*HID, hW[6] + (size_t)l*DIMM);

    save_cls_kernel<<<(BATCH*DIMM + 255)/256, 256>>>(P.gx, P.gcls);

    for (int l = 0; l < L_TAIL; l++)
        run_layer(4 + l, P, tW[2] + (size_t)l*DIMM, tW[4] + (size_t)l*HID, tW[6] + (size_t)l*DIMM);

    {
        int total = MROWS * DIMM + BATCH * DIMM;
        write_out_kernel<<<(total + 255)/256, 256>>>(P.gx, P.gcls, (float*)d_out);
    }
}

// round 17
// speedup vs baseline: 1.4639x; 1.4125x over previous
#include <cuda_runtime.h>
#include <cuda_fp16.h>
#include <math.h>
#include <stdint.h>

// ---------------- problem constants ----------------
#define DIMM   1024
#define NHEADS 8
#define DHEAD  128
#define NTOK   2049
#define BATCH  2
#define MROWS  (BATCH*NTOK)  // 4098
#define HID    4096
#define L_HEAD 4
#define L_TAIL 4

// ---------------- scratch (device globals) ----------------
__device__ __align__(16) float g_x  [(size_t)MROWS*DIMM];
__device__ __align__(16) float g_cls[(size_t)BATCH*DIMM];

// activation fp16 hi/lo planes (word = 2 halfs along N)
__device__ __align__(16) unsigned g_xs_h[(size_t)MROWS*DIMM/2];
__device__ __align__(16) unsigned g_xs_l[(size_t)MROWS*DIMM/2];
__device__ __align__(16) unsigned g_as_h[(size_t)MROWS*DIMM/2];
__device__ __align__(16) unsigned g_as_l[(size_t)MROWS*DIMM/2];
__device__ __align__(16) unsigned g_hs_h[(size_t)MROWS*HID/2];
__device__ __align__(16) unsigned g_hs_l[(size_t)MROWS*HID/2];
__device__ __align__(16) unsigned g_qs_h[(size_t)MROWS*3*DIMM/2];
__device__ __align__(16) unsigned g_qs_l[(size_t)MROWS*3*DIMM/2];

// weights: SINGLE fp16 plane, frag-pair layout:
//   word offset (per layer) = (g8*N + n)*8 + q*2 + h,  k2 = 8*g8 + q + 4*h
#define WQKV_L (512*3072)
#define WO_L   (512*1024)
#define W1_L   (512*4096)
#define W2_L   (2048*1024)
__device__ __align__(16) unsigned g_wqkv_h[8*(size_t)WQKV_L];
__device__ __align__(16) unsigned g_wo_h[8*(size_t)WO_L];
__device__ __align__(16) unsigned g_w1_h[8*(size_t)W1_L];
__device__ __align__(16) unsigned g_w2_h[8*(size_t)W2_L];

// ---------------- fp16 helpers ----------------
__device__ __forceinline__ unsigned short f2h(float x) {
    __half h = __float2half(x);
    return *reinterpret_cast<unsigned short*>(&h);
}
__device__ __forceinline__ float h2f(unsigned short s) {
    __half h = *reinterpret_cast<__half*>(&s);
    return __half2float(h);
}
// split a,b into fp16 hi/lo packed words
__device__ __forceinline__ void split_pair16(float a, float b, unsigned& hw, unsigned& lw) {
    unsigned short ah = f2h(a);
    unsigned short al = f2h(a - h2f(ah));
    unsigned short bh = f2h(b);
    unsigned short bl = f2h(b - h2f(bh));
    hw = (unsigned)ah | ((unsigned)bh << 16);
    lw = (unsigned)al | ((unsigned)bl << 16);
}
// round pair to single fp16 word
__device__ __forceinline__ unsigned pack16(float a, float b) {
    return (unsigned)f2h(a) | ((unsigned)f2h(b) << 16);
}

__device__ __forceinline__ void mma_f16(float* c, const unsigned* a, const unsigned* b) {
    asm("mma.sync.aligned.m16n8k16.row.col.f32.f16.f16.f32 "
        "{%0,%1,%2,%3}, {%4,%5,%6,%7}, {%8,%9}, {%0,%1,%2,%3};"
        : "+f"(c[0]), "+f"(c[1]), "+f"(c[2]), "+f"(c[3])
        : "r"(a[0]), "r"(a[1]), "r"(a[2]), "r"(a[3]),
          "r"(b[0]), "r"(b[1]));
}

__device__ __forceinline__ void ldsm4(unsigned* r, const void* p) {
    unsigned a = (unsigned)__cvta_generic_to_shared(p);
    asm volatile("ldmatrix.sync.aligned.m8n8.x4.shared.b16 {%0,%1,%2,%3}, [%4];"
        : "=r"(r[0]), "=r"(r[1]), "=r"(r[2]), "=r"(r[3]) : "r"(a));
}

__device__ __forceinline__ void cpa16(void* dst, const void* src, int sz) {
    unsigned d = (unsigned)__cvta_generic_to_shared(dst);
    asm volatile("cp.async.cg.shared.global [%0], [%1], 16, %2;" :: "r"(d), "l"(src), "r"(sz));
}
__device__ __forceinline__ void cp_commit() { asm volatile("cp.async.commit_group;"); }
template<int N> __device__ __forceinline__ void cp_wait() {
    asm volatile("cp.async.wait_group %0;" :: "n"(N));
}

// ---------------- weight pre-split kernel (single fp16 plane, frag-pair layout) ---------
__global__ void split_w2_kernel(const float* __restrict__ Wh, const float* __restrict__ Wt,
                                unsigned* __restrict__ oH, int K, int N)
{
    __shared__ unsigned smh[8][257];
    int l = blockIdx.z;
    const float* W = (l < 4) ? (Wh + (size_t)l * K * N) : (Wt + (size_t)(l - 4) * K * N);
    int g8 = blockIdx.y;
    int n0 = blockIdx.x * 256;
    int tx = threadIdx.x;
#pragma unroll
    for (int r = 0; r < 8; r++) {
        int k2 = g8 * 8 + r;
        float a = W[(size_t)(2 * k2) * N + n0 + tx];
        float b = W[(size_t)(2 * k2 + 1) * N + n0 + tx];
        smh[r][tx] = pack16(a, b);
    }
    __syncthreads();
    size_t base = (size_t)l * ((size_t)K * N / 2) + ((size_t)g8 * N + n0 + tx) * 8;
    unsigned vh[8];
#pragma unroll
    for (int j = 0; j < 8; j++) {
        int r = (j >> 1) + 4 * (j & 1);
        vh[j] = smh[r][tx];
    }
    *(uint4*)(oH + base)     = make_uint4(vh[0], vh[1], vh[2], vh[3]);
    *(uint4*)(oH + base + 4) = make_uint4(vh[4], vh[5], vh[6], vh[7]);
}

// ---------------- concat cls + x ----------------
__global__ void concat_kernel(const float* __restrict__ x, const float* __restrict__ cls,
                              float* __restrict__ gx,
                              unsigned* __restrict__ xh, unsigned* __restrict__ xl)
{
    int idx = blockIdx.x * blockDim.x + threadIdx.x;
    int total = MROWS * DIMM / 2;
    if (idx >= total) return;
    int c2  = idx % (DIMM / 2);
    int row = idx / (DIMM / 2);
    int n = row % NTOK, b = row / NTOK;
    float v0, v1;
    if (n == 0) { v0 = cls[c2 * 2]; v1 = cls[c2 * 2 + 1]; }
    else {
        const float* p = x + ((size_t)b * (NTOK - 1) + (n - 1)) * DIMM + c2 * 2;
        v0 = p[0]; v1 = p[1];
    }
    gx[idx * 2] = v0; gx[idx * 2 + 1] = v1;
    unsigned hw, lw;
    split_pair16(v0, v1, hw, lw);
    xh[idx] = hw; xl[idx] = lw;
}

// ---------------- tensor-core GEMM: fp16 2-pass, 8 warps 64x32, 3-stage, 2 CTAs/SM ------
#define AST_B 80
#define STG_A (128*AST_B)               // 10240 per A plane
#define BGRP  1032                      // words per k-group (1024 data + 8 pad)
#define STG_B4 (2*BGRP*4)               // 8256 bytes (single B plane)
#define STG_BYTES (2*STG_A + STG_B4)    // 28736
#define NSTAGE 3
#define SM_TOTAL (NSTAGE*STG_BYTES)     // 86208

template<bool BIAS, bool RESID, bool DOGELU, bool W32, bool WS>
__global__ __launch_bounds__(256, 2)
void tgemm_kernel(const unsigned* __restrict__ AH, const unsigned* __restrict__ AL,
                  const unsigned* __restrict__ BH,
                  const float* __restrict__ bias, const float* __restrict__ R,
                  float* __restrict__ C,
                  unsigned* __restrict__ OH, unsigned* __restrict__ OL,
                  int M, int K, int N)
{
    extern __shared__ char smem[];

    const int t    = threadIdx.x;
    const int warp = t >> 5;
    const int lane = t & 31;
    const int g    = lane >> 2;
    const int q    = lane & 3;
    const int wm   = warp & 1;
    const int wn   = warp >> 1;
    const int bm   = blockIdx.y * 128;
    const int bn   = blockIdx.x * 128;
    const int steps = K >> 5;

    float acc[4][4][4];
#pragma unroll
    for (int i = 0; i < 4; i++)
#pragma unroll
        for (int j = 0; j < 4; j++)
#pragma unroll
            for (int e = 0; e < 4; e++) acc[i][j][e] = 0.f;

    const int ar0 = t >> 2,  ac0 = (t & 3);
    const int ar1 = (t + 256) >> 2, ac1 = (t & 3);

    const unsigned short* AHg = (const unsigned short*)AH;
    const unsigned short* ALg = (const unsigned short*)AL;

    auto issue = [&](int s) {
        char* buf = smem + (s % NSTAGE) * STG_BYTES;
        char* AHs = buf;
        char* ALs = buf + STG_A;
        char* BHs = buf + 2 * STG_A;
        int k0 = s * 32;
        {
            int gr = bm + ar0;
            int sz = (gr < M) ? 16 : 0;
            size_t so = (size_t)(gr < M ? gr : 0) * K + k0 + ac0 * 8;
            cpa16(AHs + ar0 * AST_B + ac0 * 16, AHg + so, sz);
            cpa16(ALs + ar0 * AST_B + ac0 * 16, ALg + so, sz);
            gr = bm + ar1;
            sz = (gr < M) ? 16 : 0;
            so = (size_t)(gr < M ? gr : 0) * K + k0 + ac1 * 8;
            cpa16(AHs + ar1 * AST_B + ac1 * 16, AHg + so, sz);
            cpa16(ALs + ar1 * AST_B + ac1 * 16, ALg + so, sz);
        }
        {
            int sgrp = s * 2;
            size_t src0 = ((size_t)sgrp * N + bn) * 8 + t * 4;
            size_t src1 = ((size_t)(sgrp + 1) * N + bn) * 8 + t * 4;
            cpa16(BHs + t * 16,            BH + src0, 16);
            cpa16(BHs + BGRP * 4 + t * 16, BH + src1, 16);
        }
        cp_commit();
    };

    issue(0);
    if (steps > 1) issue(1);

    const int lanebase = (wm * 64 + (lane & 7) + ((lane >> 3) & 1) * 8) * AST_B + (lane >> 4) * 16;

    for (int s = 0; s < steps; s++) {
        if (s + 1 < steps) cp_wait<1>();
        else               cp_wait<0>();
        __syncthreads();

        if (s + 2 < steps) issue(s + 2);

        const char* buf = smem + (s % NSTAGE) * STG_BYTES;
        const char* AHs = buf;
        const char* ALs = buf + STG_A;
        const unsigned* BHw = (const unsigned*)(buf + 2 * STG_A);

#pragma unroll
        for (int ko = 0; ko < 2; ko++) {
            unsigned bh[4][2];
#pragma unroll
            for (int ni = 0; ni < 4; ni++) {
                int ad = ko * BGRP + (wn * 32 + g + ni * 8) * 8 + q * 2;
                uint2 vh2 = *(const uint2*)(BHw + ad);
                bh[ni][0] = vh2.x; bh[ni][1] = vh2.y;
            }
#pragma unroll
            for (int mi = 0; mi < 4; mi++) {
                unsigned ah[4], al[4];
                ldsm4(ah, AHs + lanebase + mi * (16 * AST_B) + ko * 32);
                ldsm4(al, ALs + lanebase + mi * (16 * AST_B) + ko * 32);
#pragma unroll
                for (int ni = 0; ni < 4; ni++) {
                    mma_f16(acc[mi][ni], ah, bh[ni]);
                    mma_f16(acc[mi][ni], al, bh[ni]);
                }
            }
        }
    }

    // ---- epilogue ----
    const int Nw = N >> 1;
#pragma unroll
    for (int mi = 0; mi < 4; mi++) {
        int r0 = bm + wm * 64 + mi * 16 + g;
#pragma unroll
        for (int ni = 0; ni < 4; ni++) {
            int cb = bn + wn * 32 + ni * 8 + 2 * q;
            float v[4];
#pragma unroll
            for (int e = 0; e < 4; e++) {
                v[e] = acc[mi][ni][e];
                if (BIAS) v[e] += bias[cb + (e & 1)];
                if (DOGELU) v[e] = 0.5f * v[e] * (1.f + erff(v[e] * 0.70710678118f));
            }
#pragma unroll
            for (int half = 0; half < 2; half++) {
                int gr = r0 + half * 8;
                if (gr >= M) continue;
                float a = v[half * 2], b = v[half * 2 + 1];
                if (RESID) {
                    float2 r2 = *(const float2*)(R + (size_t)gr * N + cb);
                    a += r2.x;
                    b += r2.y;
                }
                if (W32) {
                    *(float2*)(C + (size_t)gr * N + cb) = make_float2(a, b);
                }
                if (WS) {
                    unsigned hw, lw;
                    split_pair16(a, b, hw, lw);
                    size_t wi = (size_t)gr * Nw + (cb >> 1);
                    OH[wi] = hw;
                    OL[wi] = lw;
                }
            }
        }
    }
}

// ---------------- flash attention: fp16 2-pass, double-buffered K/V ----------------------
// planes: QH | QL | KH x2 | VH x2  (4352 words each)
#define ATT_PW 4352
#define ATT_SMEM (6*ATT_PW*4)   // 104448 bytes

__global__ __launch_bounds__(128, 1)
void fattn_kernel(const unsigned* __restrict__ QVH, const unsigned* __restrict__ QVL,
                  unsigned* __restrict__ OH, unsigned* __restrict__ OL)
{
    extern __shared__ unsigned smw[];
    unsigned* QH = smw;
    unsigned* QL = QH + ATT_PW;
    unsigned* KH = QL + ATT_PW;        // 2 buffers
    unsigned* VH = KH + 2*ATT_PW;      // 2 buffers

    const int t    = threadIdx.x;
    const int lane = t & 31;
    const int w    = t >> 5;
    const int g    = lane >> 2;
    const int q    = lane & 3;
    const int qt   = 32 - blockIdx.x;
    const int bh   = blockIdx.y;
    const int h    = bh & 7;
    const int b    = bh >> 3;
    const float scale = 0.03125f;

    const unsigned* bHp = QVH + (size_t)b * NTOK * 1536;
    const unsigned* bLp = QVL + (size_t)b * NTOK * 1536;

    unsigned vpre[8][4];

    auto stageK = [&](int jt, int p) {
        unsigned* KHp = KH + p * ATT_PW;
#pragma unroll
        for (int i = 0; i < 8; i++) {
            int idx = i * 128 + t;
            int key = idx >> 4;
            int c4w = (idx & 15) * 4;
            int gkey = jt * 64 + key;
            int sz = (gkey < NTOK) ? 16 : 0;
            size_t gw = (size_t)(gkey < NTOK ? gkey : 0) * 1536 + 512 + h * 64 + c4w;
            cpa16(KHp + key * 68 + c4w, bHp + gw, sz);
        }
        cp_commit();
    };

    auto loadV = [&](int jt) {
#pragma unroll
        for (int i = 0; i < 8; i++) {
            int idx = i * 128 + t;
            int kp = idx >> 5;
            int cg = idx & 31;
            int k0g = jt * 64 + 2 * kp;
            uint2 wh = make_uint2(0,0), uh = make_uint2(0,0);
            if (k0g < NTOK) {
                size_t gw = (size_t)k0g * 1536 + 1024 + h * 64 + 2 * cg;
                wh = *(const uint2*)(bHp + gw);
            }
            if (k0g + 1 < NTOK) {
                size_t gw = (size_t)(k0g + 1) * 1536 + 1024 + h * 64 + 2 * cg;
                uh = *(const uint2*)(bHp + gw);
            }
            vpre[i][0] = wh.x; vpre[i][1] = wh.y; vpre[i][2] = uh.x; vpre[i][3] = uh.y;
        }
    };

    auto stsV = [&](int p) {
        unsigned* VHp = VH + p * ATT_PW;
#pragma unroll
        for (int i = 0; i < 8; i++) {
            int idx = i * 128 + t;
            int kp = idx >> 5;
            int cg = idx & 31;
            int wb = kp * 136 + 4 * cg;
            VHp[wb + 0] = __byte_perm(vpre[i][0], vpre[i][2], 0x5410);
            VHp[wb + 1] = __byte_perm(vpre[i][0], vpre[i][2], 0x7632);
            VHp[wb + 2] = __byte_perm(vpre[i][1], vpre[i][3], 0x5410);
            VHp[wb + 3] = __byte_perm(vpre[i][1], vpre[i][3], 0x7632);
        }
    };

    stageK(0, 0);
    loadV(0);
#pragma unroll
    for (int i = 0; i < 8; i++) {
        int idx = i * 128 + t;
        int row = idx >> 4;
        int c4w = (idx & 15) * 4;
        int grow = qt * 64 + row;
        uint4 vh = make_uint4(0,0,0,0), vl = make_uint4(0,0,0,0);
        if (grow < NTOK) {
            size_t gw = (size_t)grow * 1536 + h * 64 + c4w;
            vh = *(const uint4*)(bHp + gw);
            vl = *(const uint4*)(bLp + gw);
        }
        *(uint4*)(QH + row * 68 + c4w) = vh;
        *(uint4*)(QL + row * 68 + c4w) = vl;
    }
    stsV(0);
    cp_wait<0>();
    __syncthreads();

    float o[16][4];
#pragma unroll
    for (int ni = 0; ni < 16; ni++)
#pragma unroll
        for (int e = 0; e < 4; e++) o[ni][e] = 0.f;
    float mrow[2] = {-1e30f, -1e30f};
    float lrow[2] = {0.f, 0.f};

    for (int jt = 0; jt <= qt; jt++) {
        const int p = jt & 1;
        const bool more = jt < qt;
        if (more) {
            stageK(jt + 1, p ^ 1);
            loadV(jt + 1);
        }

        const unsigned* KHp = KH + p * ATT_PW;
        const unsigned* VHp = VH + p * ATT_PW;

        // ---- S = Q @ K^T (2-pass fp16) ----
        float s[8][4];
#pragma unroll
        for (int ni = 0; ni < 8; ni++)
#pragma unroll
            for (int e = 0; e < 4; e++) s[ni][e] = 0.f;

        const int r0 = w * 16 + g;
#pragma unroll
        for (int ko = 0; ko < 8; ko++) {
            unsigned qh[4], ql[4];
            int w0 = r0 * 68 + q + ko * 8;
            int w1 = (r0 + 8) * 68 + q + ko * 8;
            qh[0] = QH[w0];     qh[1] = QH[w1];
            qh[2] = QH[w0 + 4]; qh[3] = QH[w1 + 4];
            ql[0] = QL[w0];     ql[1] = QL[w1];
            ql[2] = QL[w0 + 4]; ql[3] = QL[w1 + 4];
#pragma unroll
            for (int ni = 0; ni < 8; ni++) {
                int nb = ni * 8 + g;
                unsigned khf[2];
                khf[0] = KHp[nb * 68 + q + ko * 8];
                khf[1] = KHp[nb * 68 + q + 4 + ko * 8];
                mma_f16(s[ni], qh, khf);
                mma_f16(s[ni], ql, khf);
            }
        }

#pragma unroll
        for (int ni = 0; ni < 8; ni++)
#pragma unroll
            for (int e = 0; e < 4; e++) s[ni][e] *= scale;

        if (jt == qt) {
            int rbase = qt * 64 + w * 16 + g;
#pragma unroll
            for (int ni = 0; ni < 8; ni++) {
                int cbase = jt * 64 + ni * 8 + 2 * q;
#pragma unroll
                for (int e = 0; e < 4; e++) {
                    int row = rbase + (e >= 2 ? 8 : 0);
                    int col = cbase + (e & 1);
                    if (col > row) s[ni][e] = -1e30f;
                }
            }
        }

        float mt[2] = {-1e30f, -1e30f};
#pragma unroll
        for (int ni = 0; ni < 8; ni++) {
            mt[0] = fmaxf(mt[0], fmaxf(s[ni][0], s[ni][1]));
            mt[1] = fmaxf(mt[1], fmaxf(s[ni][2], s[ni][3]));
        }
#pragma unroll
        for (int d = 1; d <= 2; d <<= 1) {
            mt[0] = fmaxf(mt[0], __shfl_xor_sync(0xFFFFFFFFu, mt[0], d));
            mt[1] = fmaxf(mt[1], __shfl_xor_sync(0xFFFFFFFFu, mt[1], d));
        }
        float mn[2] = {fmaxf(mrow[0], mt[0]), fmaxf(mrow[1], mt[1])};
        float corr[2] = {__expf(mrow[0] - mn[0]), __expf(mrow[1] - mn[1])};

        float rs[2] = {0.f, 0.f};
#pragma unroll
        for (int ni = 0; ni < 8; ni++) {
#pragma unroll
            for (int e = 0; e < 4; e++) {
                float pv = __expf(s[ni][e] - mn[e >> 1]);
                s[ni][e] = pv;
                rs[e >> 1] += pv;
            }
        }
#pragma unroll
        for (int d = 1; d <= 2; d <<= 1) {
            rs[0] += __shfl_xor_sync(0xFFFFFFFFu, rs[0], d);
            rs[1] += __shfl_xor_sync(0xFFFFFFFFu, rs[1], d);
        }
        lrow[0] = lrow[0] * corr[0] + rs[0];
        lrow[1] = lrow[1] * corr[1] + rs[1];
        mrow[0] = mn[0];
        mrow[1] = mn[1];
#pragma unroll
        for (int ni = 0; ni < 16; ni++) {
            o[ni][0] *= corr[0]; o[ni][1] *= corr[0];
            o[ni][2] *= corr[1]; o[ni][3] *= corr[1];
        }

        // ---- O += P @ V (2-pass fp16: P split, V single) ----
#pragma unroll
        for (int kp = 0; kp < 4; kp++) {
            unsigned ph[4], pl[4];
            split_pair16(s[2*kp][0],   s[2*kp][1],   ph[0], pl[0]);
            split_pair16(s[2*kp][2],   s[2*kp][3],   ph[1], pl[1]);
            split_pair16(s[2*kp+1][0], s[2*kp+1][1], ph[2], pl[2]);
            split_pair16(s[2*kp+1][2], s[2*kp+1][3], ph[3], pl[3]);
#pragma unroll
            for (int ni = 0; ni < 16; ni++) {
                int nb = ni * 8 + g;
                unsigned vhf[2];
                vhf[0] = VHp[(q + kp * 8) * 136 + nb];
                vhf[1] = VHp[(q + 4 + kp * 8) * 136 + nb];
                mma_f16(o[ni], ph, vhf);
                mma_f16(o[ni], pl, vhf);
            }
        }

        if (more) {
            stsV(p ^ 1);
            cp_wait<0>();
        }
        __syncthreads();
    }

    float inv[2] = {1.f / lrow[0], 1.f / lrow[1]};
    int rbase = qt * 64 + w * 16 + g;
#pragma unroll
    for (int ni = 0; ni < 16; ni++) {
        int cb = h * DHEAD + ni * 8 + 2 * q;
#pragma unroll
        for (int half = 0; half < 2; half++) {
            int row = rbase + half * 8;
            if (row >= NTOK) continue;
            unsigned hw, lw;
            split_pair16(o[ni][half*2] * inv[half], o[ni][half*2+1] * inv[half], hw, lw);
            size_t wi = (size_t)(b * NTOK + row) * (DIMM / 2) + (cb >> 1);
            OH[wi] = hw;
            OL[wi] = lw;
        }
    }
}

// ---------------- small kernels ----------------
__global__ void save_cls_kernel(const float* __restrict__ gx, float* __restrict__ gcls)
{
    int idx = blockIdx.x * blockDim.x + threadIdx.x;
    if (idx >= BATCH * DIMM) return;
    int b = idx / DIMM, d = idx % DIMM;
    gcls[idx] = gx[((size_t)b * NTOK) * DIMM + d];
}

__global__ void write_out_kernel(const float* __restrict__ gx,
                                 const float* __restrict__ gcls,
                                 float* __restrict__ out)
{
    const int totalx = MROWS * DIMM;
    const int totalc = BATCH * DIMM;
    int idx = blockIdx.x * blockDim.x + threadIdx.x;
    if (idx < totalx)               out[idx] = gx[idx];
    else if (idx < totalx + totalc) out[idx] = gcls[idx - totalx];
}

// ---------------- host orchestration ----------------
struct DevPtrs {
    float *gx, *gcls;
    unsigned *xsh, *xsl, *ash, *asl, *hsh, *hsl, *qsh, *qsl;
    unsigned *wqh, *woh, *w1h, *w2h;
};

static void run_layer(int l, const DevPtrs& P,
                      const float* bo, const float* b1, const float* b2)
{
    const int gy = (MROWS + 127) / 128;  // 33
    tgemm_kernel<false,false,false,false,true><<<dim3(24, gy), 256, SM_TOTAL>>>(
        P.xsh, P.xsl, P.wqh + (size_t)l*WQKV_L,
        nullptr, nullptr, nullptr, P.qsh, P.qsl, MROWS, DIMM, 3*DIMM);
    fattn_kernel<<<dim3(33, BATCH*NHEADS), 128, ATT_SMEM>>>(P.qsh, P.qsl, P.ash, P.asl);
    tgemm_kernel<true,true,false,true,true><<<dim3(8, gy), 256, SM_TOTAL>>>(
        P.ash, P.asl, P.woh + (size_t)l*WO_L,
        bo, P.gx, P.gx, P.xsh, P.xsl, MROWS, DIMM, DIMM);
    tgemm_kernel<true,false,true,false,true><<<dim3(32, gy), 256, SM_TOTAL>>>(
        P.xsh, P.xsl, P.w1h + (size_t)l*W1_L,
        b1, nullptr, nullptr, P.hsh, P.hsl, MROWS, DIMM, HID);
    tgemm_kernel<true,true,false,true,true><<<dim3(8, gy), 256, SM_TOTAL>>>(
        P.hsh, P.hsl, P.w2h + (size_t)l*W2_L,
        b2, P.gx, P.gx, P.xsh, P.xsl, MROWS, HID, DIMM);
}

extern "C" void kernel_launch(void* const* d_in, const int* in_sizes, int n_in,
                              void* d_out, int out_size)
{
    const float* x_in = (const float*)d_in[0];
    const float* cls  = (const float*)d_in[1];
    const float* hW[7];
    const float* tW[7];
    for (int i = 0; i < 7; i++) hW[i] = (const float*)d_in[2 + i];
    for (int i = 0; i < 7; i++) tW[i] = (const float*)d_in[9 + i];

    cudaFuncSetAttribute(tgemm_kernel<false,false,false,false,true>,
                         cudaFuncAttributeMaxDynamicSharedMemorySize, SM_TOTAL);
    cudaFuncSetAttribute(tgemm_kernel<true,true,false,true,true>,
                         cudaFuncAttributeMaxDynamicSharedMemorySize, SM_TOTAL);
    cudaFuncSetAttribute(tgemm_kernel<true,false,true,false,true>,
                         cudaFuncAttributeMaxDynamicSharedMemorySize, SM_TOTAL);
    cudaFuncSetAttribute(fattn_kernel,
                         cudaFuncAttributeMaxDynamicSharedMemorySize, ATT_SMEM);

    DevPtrs P;
    cudaGetSymbolAddress((void**)&P.gx,   g_x);
    cudaGetSymbolAddress((void**)&P.gcls, g_cls);
    cudaGetSymbolAddress((void**)&P.xsh,  g_xs_h);
    cudaGetSymbolAddress((void**)&P.xsl,  g_xs_l);
    cudaGetSymbolAddress((void**)&P.ash,  g_as_h);
    cudaGetSymbolAddress((void**)&P.asl,  g_as_l);
    cudaGetSymbolAddress((void**)&P.hsh,  g_hs_h);
    cudaGetSymbolAddress((void**)&P.hsl,  g_hs_l);
    cudaGetSymbolAddress((void**)&P.qsh,  g_qs_h);
    cudaGetSymbolAddress((void**)&P.qsl,  g_qs_l);
    cudaGetSymbolAddress((void**)&P.wqh,  g_wqkv_h);
    cudaGetSymbolAddress((void**)&P.woh,  g_wo_h);
    cudaGetSymbolAddress((void**)&P.w1h,  g_w1_h);
    cudaGetSymbolAddress((void**)&P.w2h,  g_w2_h);

    split_w2_kernel<<<dim3(3072/256, 1024/16, 8), 256>>>(hW[0], tW[0], P.wqh, 1024, 3072);
    split_w2_kernel<<<dim3(1024/256, 1024/16, 8), 256>>>(hW[1], tW[1], P.woh, 1024, 1024);
    split_w2_kernel<<<dim3(4096/256, 1024/16, 8), 256>>>(hW[3], tW[3], P.w1h, 1024, 4096);
    split_w2_kernel<<<dim3(1024/256, 4096/16, 8), 256>>>(hW[5], tW[5], P.w2h, 4096, 1024);

    {
        int total = MROWS * DIMM / 2;
        concat_kernel<<<(total + 255) / 256, 256>>>(x_in, cls, P.gx, P.xsh, P.xsl);
    }

    for (int l = 0; l < L_HEAD; l++)
        run_layer(l, P, hW[2] + (size_t)l*DIMM, hW[4] + (size_t)l*HID, hW[6] + (size_t)l*DIMM);

    save_cls_kernel<<<(BATCH*DIMM + 255)/256, 256>>>(P.gx, P.gcls);

    for (int l = 0; l < L_TAIL; l++)
        run_layer(4 + l, P, tW[2] + (size_t)l*DIMM, tW[4] + (size_t)l*HID, tW[6] + (size_t)l*DIMM);

    {
        int total = MROWS * DIMM + BATCH * DIMM;
        write_out_kernel<<<(total + 255)/256, 256>>>(P.gx, P.gcls, (float*)d_out);
    }
}